// round 8
// baseline (speedup 1.0000x reference)
#include <cuda_runtime.h>
#include <math_constants.h>

// ---------------------------------------------------------------------------
// Exact 3-NN interpolation via grid ring-search — fused persistent kernel, v3.
//   phase 0: init occupancy maps + worklist counter
//   phase 1: scatter rows (atomicMin cascade keeps 3 lowest rows per cell)
//   phase 2: THREAD-per-(point,scale) 27-cell search; tasks failing the
//            rr=1 stop bound go to a worklist
//   phase 3: warp-cooperative ring search for worklist tasks (rare)
//   phase 4: thread-per-float4 gather (coalesced)
// Grid barriers: sense-reversing, self-cleaning. GRID=592 = 4 blocks/SM x 148,
// __launch_bounds__(256,4) -> all blocks co-resident, no deadlock.
//
// Exactness: all candidate (d2,row) pairs form a total lexicographic order
// (rows globally unique per scale), so per-thread strict insertion yields the
// same top-3 as jax.lax.top_k (stable, duplicate voxels have bitwise-equal
// d2 and per-cell slots sorted by row). Stop rule: after the 27-cell cube,
// any unexamined center is >= 1.5*vs away (point inside its own cell); >=3
// candidates strictly inside that bound (shrunk conservatively) => exact.
// Distance math: explicit __fmul_rn/__fadd_rn in reference op order.
// ---------------------------------------------------------------------------

#define NPTS   8192
#define OUTC   480
#define INF_I  0x7fffffff
#define INF_FB 0x7f800000u

#define MB0 0
#define MB1 32768
#define MB2 (32768 + 4096)
#define MB3 (32768 + 4096 + 512)
#define MCELLS (32768 + 4096 + 512 + 64)

#define GRID     592                   // 4 blocks/SM * 148 SMs, all resident
#define TPB      256
#define NTHREADS (GRID * TPB)          // 151552
#define NWARPS   (NTHREADS / 32)       // 4736
#define NTASKS   (NPTS * 4)            // 32768
#define NROWS    20576                 // 16000 + 4000 + 512 + 64
#define NF4      (NPTS * 120)          // 983040 float4 outputs

__device__ int4     g_map[MCELLS];
__device__ float4   g_w[NTASKS];       // weights per task
__device__ int4     g_r[NTASKS];       // rows per task
__device__ int      g_wl[NTASKS];      // fallback worklist
__device__ unsigned g_wl_cnt;
__device__ unsigned g_cnt[4];
__device__ unsigned g_phase[4];        // monotone senses; never reset

__device__ __forceinline__ void grid_bar(int b)
{
    __syncthreads();
    if (threadIdx.x == 0) {
        volatile unsigned* ph = &g_phase[b];
        unsigned p0 = *ph;
        __threadfence();
        unsigned prev = atomicAdd(&g_cnt[b], 1u);
        if (prev == GRID - 1) {
            g_cnt[b] = 0;
            __threadfence();
            *ph = p0 + 1u;
        } else {
            while (*ph == p0) { }
        }
        __threadfence();
    }
    __syncthreads();
}

__device__ __forceinline__ bool diless(float da, int ia, float db, int ib) {
    return (da < db) || (da == db && ia < ib);
}

__device__ __forceinline__ void ins3(float d, int i,
                                     float& d0, int& i0,
                                     float& d1, int& i1,
                                     float& d2, int& i2) {
    if (diless(d, i, d2, i2)) {
        d2 = d; i2 = i;
        if (diless(d2, i2, d1, i1)) { float td = d1; d1 = d2; d2 = td; int ti = i1; i1 = i2; i2 = ti; }
        if (diless(d1, i1, d0, i0)) { float td = d0; d0 = d1; d1 = td; int ti = i0; i0 = i1; i1 = ti; }
    }
}

__device__ __forceinline__ void visit_cell(
    int jx, int jy, int jz, int g, int base,
    float vs, float OFF, float HALF,
    float px, float py, float pz,
    float& d0, int& r0, float& d1, int& r1, float& d2, int& r2)
{
    if ((unsigned)jx >= (unsigned)g || (unsigned)jy >= (unsigned)g ||
        (unsigned)jz >= (unsigned)g) return;

    int4 s = g_map[base + (jx * g + jy) * g + jz];
    if (s.x == INF_I) return;

    float qx = __fadd_rn(__fadd_rn(__fmul_rn((float)jx, vs), OFF), HALF);
    float qy = __fadd_rn(__fadd_rn(__fmul_rn((float)jy, vs), OFF), HALF);
    float qz = __fadd_rn(__fadd_rn(__fmul_rn((float)jz, vs), OFF), HALF);
    float ddx = px - qx, ddy = py - qy, ddz = pz - qz;
    float dd = __fadd_rn(__fadd_rn(__fmul_rn(ddx, ddx), __fmul_rn(ddy, ddy)),
                         __fmul_rn(ddz, ddz));

    ins3(dd, s.x, d0, r0, d1, r1, d2, r2);
    if (s.y != INF_I) {
        ins3(dd, s.y, d0, r0, d1, r1, d2, r2);
        if (s.z != INF_I) ins3(dd, s.z, d0, r0, d1, r1, d2, r2);
    }
}

__device__ __forceinline__ void scale_params(int scale, const float* f0,
    const float* f1, const float* f2, const float* f3,
    const float*& f, float& vs, int& g, int& base)
{
    switch (scale) {
        case 0:  f = f0; vs = 0.015f * 2.0f;  g = 32; base = MB0; break;
        case 1:  f = f1; vs = 0.015f * 4.0f;  g = 16; base = MB1; break;
        case 2:  f = f2; vs = 0.015f * 8.0f;  g = 8;  base = MB2; break;
        default: f = f3; vs = 0.015f * 16.0f; g = 4;  base = MB3; break;
    }
}

__device__ __forceinline__ void store_result(int task, float d0, float d1,
                                             float d2, int r0, int r1, int r2)
{
    float a0 = 1.0f / (d0 + 1e-8f);
    float a1 = 1.0f / (d1 + 1e-8f);
    float a2 = 1.0f / (d2 + 1e-8f);
    float inv = 1.0f / (a0 + a1 + a2);
    g_w[task] = make_float4(a0 * inv, a1 * inv, a2 * inv, 0.0f);
    g_r[task] = make_int4(r0, r1, r2, 0);
}

// ---------------------------------------------------------------------------
__global__ void __launch_bounds__(TPB, 4)
fused(const float* __restrict__ pts,
      const int* __restrict__ x0, const int* __restrict__ x1,
      const int* __restrict__ x2, const int* __restrict__ x3,
      const float* __restrict__ f0, const float* __restrict__ f1,
      const float* __restrict__ f2, const float* __restrict__ f3,
      float* __restrict__ out)
{
    int gtid = blockIdx.x * TPB + threadIdx.x;
    const float OFF = -0.48f;                        // (-0.5*0.015f)*64, exact

    // ---- phase 0: init ----
    if (gtid == 0) g_wl_cnt = 0;
    for (int i = gtid; i < MCELLS; i += NTHREADS)
        g_map[i] = make_int4(INF_I, INF_I, INF_I, INF_I);
    grid_bar(0);

    // ---- phase 1: scatter rows (3 lowest rows per cell, sorted) ----
    if (gtid < NROWS) {
        int t = gtid;
        const int* inds; int g, base, row;
        if (t < 16000)      { inds = x0; g = 32; base = MB0; row = t; }
        else if (t < 20000) { inds = x1; g = 16; base = MB1; row = t - 16000; }
        else if (t < 20512) { inds = x2; g = 8;  base = MB2; row = t - 20000; }
        else                { inds = x3; g = 4;  base = MB3; row = t - 20512; }
        int4 v = ((const int4*)inds)[row];           // [batch, ix, iy, iz]
        int* s = (int*)&g_map[base + (v.y * g + v.z) * g + v.w];
        int cur = row;
#pragma unroll
        for (int k = 0; k < 3; k++) {
            int old = atomicMin(&s[k], cur);
            cur = max(old, cur);
            if (cur == INF_I) break;
        }
    }
    grid_bar(1);

    // ---- phase 2: thread-per-task 27-cell search ----
    if (gtid < NTASKS) {
        int task = gtid;
        int scale = task >> 13, point = task & (NPTS - 1);  // scale-major
        const float* f; float vs; int g, base;
        scale_params(scale, f0, f1, f2, f3, f, vs, g, base);
        const float HALF = 0.5f * vs;

        float px = __ldg(&pts[point * 3 + 0]);
        float py = __ldg(&pts[point * 3 + 1]);
        float pz = __ldg(&pts[point * 3 + 2]);

        int cx = min(g - 1, max(0, (int)floorf((px - OFF) / vs)));
        int cy = min(g - 1, max(0, (int)floorf((py - OFF) / vs)));
        int cz = min(g - 1, max(0, (int)floorf((pz - OFF) / vs)));

        float d0 = CUDART_INF_F, d1 = CUDART_INF_F, d2 = CUDART_INF_F;
        int   r0 = INF_I,        r1 = INF_I,        r2 = INF_I;

#pragma unroll
        for (int dx = -1; dx <= 1; dx++)
#pragma unroll
            for (int dy = -1; dy <= 1; dy++)
#pragma unroll
                for (int dz = -1; dz <= 1; dz++)
                    visit_cell(cx + dx, cy + dy, cz + dz, g, base, vs, OFF,
                               HALF, px, py, pz, d0, r0, d1, r1, d2, r2);

        float b  = 1.5f * vs * 0.999999f;
        float b2 = b * b;
        if ((int)(d0 < b2) + (int)(d1 < b2) + (int)(d2 < b2) >= 3) {
            store_result(task, d0, d1, d2, r0, r1, r2);
        } else {
            g_wl[atomicAdd(&g_wl_cnt, 1u)] = task;   // rare fallback
        }
    }
    grid_bar(2);

    // ---- phase 3: warp-cooperative ring search for worklist tasks ----
    {
        int warp = gtid >> 5;
        int lane = threadIdx.x & 31;
        unsigned wln = *(volatile unsigned*)&g_wl_cnt;

        for (unsigned e = warp; e < wln; e += NWARPS) {
            int task = g_wl[e];
            int scale = task >> 13, point = task & (NPTS - 1);
            const float* f; float vs; int g, base;
            scale_params(scale, f0, f1, f2, f3, f, vs, g, base);
            const float HALF = 0.5f * vs;

            float px = __ldg(&pts[point * 3 + 0]);
            float py = __ldg(&pts[point * 3 + 1]);
            float pz = __ldg(&pts[point * 3 + 2]);

            int cx = min(g - 1, max(0, (int)floorf((px - OFF) / vs)));
            int cy = min(g - 1, max(0, (int)floorf((py - OFF) / vs)));
            int cz = min(g - 1, max(0, (int)floorf((pz - OFF) / vs)));

            float d0 = CUDART_INF_F, d1 = CUDART_INF_F, d2 = CUDART_INF_F;
            int   r0 = INF_I,        r1 = INF_I,        r2 = INF_I;

            int rr = 1;
            bool first = true;
            while (true) {
                int side = 2 * rr + 1;
                int nc = side * side * side;
                for (int i = lane; i < nc; i += 32) {
                    int t = i;
                    int dz = t % side; t /= side;
                    int dy = t % side;
                    int dx = t / side;
                    dx -= rr; dy -= rr; dz -= rr;
                    if (!first) {
                        int ch = max(max(abs(dx), abs(dy)), abs(dz));
                        if (ch < rr) continue;
                    }
                    visit_cell(cx + dx, cy + dy, cz + dz, g, base, vs, OFF,
                               HALF, px, py, pz, d0, r0, d1, r1, d2, r2);
                }
                float bb  = ((float)rr + 0.5f) * vs * 0.999999f;
                float bb2 = bb * bb;
                int c = (int)(d0 < bb2) + (int)(d1 < bb2) + (int)(d2 < bb2);
                if (__reduce_add_sync(0xffffffffu, c) >= 3) break;
                if (rr >= g) break;                  // full grid -> exact
                rr++;
                first = false;
            }

            // REDUX 3-way head merge (rows unique across lanes)
            unsigned h0 = __float_as_uint(d0), h1 = __float_as_uint(d1),
                     h2 = __float_as_uint(d2);
            float wd[3]; int wr[3];
#pragma unroll
            for (int k = 0; k < 3; k++) {
                unsigned m  = __reduce_min_sync(0xffffffffu, h0);
                unsigned rm = __reduce_min_sync(0xffffffffu,
                                  (h0 == m) ? (unsigned)r0 : (unsigned)INF_I);
                wd[k] = __uint_as_float(m); wr[k] = (int)rm;
                if (h0 == m && (unsigned)r0 == rm) {
                    h0 = h1; r0 = r1; h1 = h2; r1 = r2; h2 = INF_FB; r2 = INF_I;
                }
            }
            if (lane == 0)
                store_result(task, wd[0], wd[1], wd[2], wr[0], wr[1], wr[2]);
        }
    }
    grid_bar(3);

    // ---- phase 4: thread-per-float4 gather (coalesced) ----
    for (int i = gtid; i < NF4; i += NTHREADS) {
        int point = i / 120;
        int c4 = i - point * 120;

        int scale, local, C4; const float* f;
        if (c4 < 8)       { scale = 0; local = c4;      C4 = 8;  f = f0; }
        else if (c4 < 24) { scale = 1; local = c4 - 8;  C4 = 16; f = f1; }
        else if (c4 < 56) { scale = 2; local = c4 - 24; C4 = 32; f = f2; }
        else              { scale = 3; local = c4 - 56; C4 = 64; f = f3; }

        int sidx = (scale << 13) | point;
        float4 w = g_w[sidx];
        int4   r = g_r[sidx];
        const float4* F = (const float4*)f;
        float4 a = F[r.x * C4 + local];
        float4 b = F[r.y * C4 + local];
        float4 d = F[r.z * C4 + local];
        float4 o;
        o.x = w.x * a.x + w.y * b.x + w.z * d.x;
        o.y = w.x * a.y + w.y * b.y + w.z * d.y;
        o.z = w.x * a.z + w.y * b.z + w.z * d.z;
        o.w = w.x * a.w + w.y * b.w + w.z * d.w;
        ((float4*)out)[i] = o;
    }
}

// ---------------------------------------------------------------------------
// Inputs identified by element count (all ten distinct):
//   points 24576 | batch_ids 8192 (all-zero, unused by reference)
//   indices: 64000 / 16000 / 2048 / 256
//   feats:   512000 / 256000 / 65536 / 16384
// ---------------------------------------------------------------------------
extern "C" void kernel_launch(void* const* d_in, const int* in_sizes, int n_in,
                              void* d_out, int out_size)
{
    const float* points = nullptr;
    const int* idx[4] = {nullptr, nullptr, nullptr, nullptr};
    const float* feats[4] = {nullptr, nullptr, nullptr, nullptr};

    for (int i = 0; i < n_in; i++) {
        switch (in_sizes[i]) {
            case 24576:  points   = (const float*)d_in[i]; break;
            case 64000:  idx[0]   = (const int*)d_in[i];   break;
            case 16000:  idx[1]   = (const int*)d_in[i];   break;
            case 2048:   idx[2]   = (const int*)d_in[i];   break;
            case 256:    idx[3]   = (const int*)d_in[i];   break;
            case 512000: feats[0] = (const float*)d_in[i]; break;
            case 256000: feats[1] = (const float*)d_in[i]; break;
            case 65536:  feats[2] = (const float*)d_in[i]; break;
            case 16384:  feats[3] = (const float*)d_in[i]; break;
            default: break; // batch_ids unused
        }
    }

    fused<<<GRID, TPB>>>(points, idx[0], idx[1], idx[2], idx[3],
                         feats[0], feats[1], feats[2], feats[3],
                         (float*)d_out);
}

// round 9
// speedup vs baseline: 1.1249x; 1.1249x over previous
#include <cuda_runtime.h>
#include <math_constants.h>

// ---------------------------------------------------------------------------
// Exact 3-NN interpolation via grid ring-search — fused persistent kernel, v4.
//   phase 0: init occupancy maps + worklist counter
//   phase 1: scatter rows (atomicMin cascade keeps 3 lowest rows per cell)
//   phase 2: QUAD-per-(point,scale): 4 lanes split the 27-cell cube (6-7
//            cells each), 2-step shfl_xor butterfly merge, local stop test.
//            Tasks failing the rr=1 bound go to a worklist.
//   phase 3: warp-cooperative ring search for worklist tasks (rare)
//   phase 4: thread-per-float4 gather (coalesced)
// Grid barriers: sense-reversing, self-cleaning. GRID=740 = 5 blocks/SM x 148,
// __launch_bounds__(256,5) -> all blocks co-resident, no deadlock.
//
// Exactness: candidate (d2,row) pairs form a total lexicographic order (rows
// globally unique per scale; duplicate voxels have bitwise-equal d2 and
// per-cell slots sorted by row), so strict lex insertion + merge yields the
// same top-3 as stable jax.lax.top_k. Quad butterfly merge: cells are
// partitioned across the 4 lanes, so exchanged lists always hold disjoint
// keys; top3(A u B) is a subset of top3(A) u top3(B), hence each step's ins3
// of the partner's 3 heads is an exact merge and all lanes converge to the
// identical sorted top-3. Stop rule: after the 27-cell cube, any unexamined
// center is >= 1.5*vs away; >=3 candidates strictly inside that bound
// (conservatively shrunk) => exact. Distance math: explicit __fmul_rn /
// __fadd_rn in reference op order (no fma contraction).
// ---------------------------------------------------------------------------

#define NPTS   8192
#define OUTC   480
#define INF_I  0x7fffffff
#define INF_FB 0x7f800000u

#define MB0 0
#define MB1 32768
#define MB2 (32768 + 4096)
#define MB3 (32768 + 4096 + 512)
#define MCELLS (32768 + 4096 + 512 + 64)

#define GRID     740                   // 5 blocks/SM * 148 SMs, all resident
#define TPB      256
#define NTHREADS (GRID * TPB)          // 189440
#define NWARPS   (NTHREADS / 32)       // 5920
#define NTASKS   (NPTS * 4)            // 32768
#define NROWS    20576                 // 16000 + 4000 + 512 + 64
#define NF4      (NPTS * 120)          // 983040 float4 outputs

__device__ int4     g_map[MCELLS];
__device__ float4   g_w[NTASKS];       // weights per task
__device__ int4     g_r[NTASKS];       // rows per task
__device__ int      g_wl[NTASKS];      // fallback worklist
__device__ unsigned g_wl_cnt;
__device__ unsigned g_cnt[4];
__device__ unsigned g_phase[4];        // monotone senses; never reset

__device__ __forceinline__ void grid_bar(int b)
{
    __syncthreads();
    if (threadIdx.x == 0) {
        volatile unsigned* ph = &g_phase[b];
        unsigned p0 = *ph;
        __threadfence();
        unsigned prev = atomicAdd(&g_cnt[b], 1u);
        if (prev == GRID - 1) {
            g_cnt[b] = 0;
            __threadfence();
            *ph = p0 + 1u;
        } else {
            while (*ph == p0) { }
        }
        __threadfence();
    }
    __syncthreads();
}

__device__ __forceinline__ bool diless(float da, int ia, float db, int ib) {
    return (da < db) || (da == db && ia < ib);
}

__device__ __forceinline__ void ins3(float d, int i,
                                     float& d0, int& i0,
                                     float& d1, int& i1,
                                     float& d2, int& i2) {
    if (diless(d, i, d2, i2)) {
        d2 = d; i2 = i;
        if (diless(d2, i2, d1, i1)) { float td = d1; d1 = d2; d2 = td; int ti = i1; i1 = i2; i2 = ti; }
        if (diless(d1, i1, d0, i0)) { float td = d0; d0 = d1; d1 = td; int ti = i0; i0 = i1; i1 = ti; }
    }
}

__device__ __forceinline__ void visit_cell(
    int jx, int jy, int jz, int g, int base,
    float vs, float OFF, float HALF,
    float px, float py, float pz,
    float& d0, int& r0, float& d1, int& r1, float& d2, int& r2)
{
    if ((unsigned)jx >= (unsigned)g || (unsigned)jy >= (unsigned)g ||
        (unsigned)jz >= (unsigned)g) return;

    int4 s = g_map[base + (jx * g + jy) * g + jz];
    if (s.x == INF_I) return;

    float qx = __fadd_rn(__fadd_rn(__fmul_rn((float)jx, vs), OFF), HALF);
    float qy = __fadd_rn(__fadd_rn(__fmul_rn((float)jy, vs), OFF), HALF);
    float qz = __fadd_rn(__fadd_rn(__fmul_rn((float)jz, vs), OFF), HALF);
    float ddx = px - qx, ddy = py - qy, ddz = pz - qz;
    float dd = __fadd_rn(__fadd_rn(__fmul_rn(ddx, ddx), __fmul_rn(ddy, ddy)),
                         __fmul_rn(ddz, ddz));

    ins3(dd, s.x, d0, r0, d1, r1, d2, r2);
    if (s.y != INF_I) {
        ins3(dd, s.y, d0, r0, d1, r1, d2, r2);
        if (s.z != INF_I) ins3(dd, s.z, d0, r0, d1, r1, d2, r2);
    }
}

__device__ __forceinline__ void scale_params(int scale, const float* f0,
    const float* f1, const float* f2, const float* f3,
    const float*& f, float& vs, int& g, int& base)
{
    switch (scale) {
        case 0:  f = f0; vs = 0.015f * 2.0f;  g = 32; base = MB0; break;
        case 1:  f = f1; vs = 0.015f * 4.0f;  g = 16; base = MB1; break;
        case 2:  f = f2; vs = 0.015f * 8.0f;  g = 8;  base = MB2; break;
        default: f = f3; vs = 0.015f * 16.0f; g = 4;  base = MB3; break;
    }
}

__device__ __forceinline__ void store_result(int task, float d0, float d1,
                                             float d2, int r0, int r1, int r2)
{
    float a0 = 1.0f / (d0 + 1e-8f);
    float a1 = 1.0f / (d1 + 1e-8f);
    float a2 = 1.0f / (d2 + 1e-8f);
    float inv = 1.0f / (a0 + a1 + a2);
    g_w[task] = make_float4(a0 * inv, a1 * inv, a2 * inv, 0.0f);
    g_r[task] = make_int4(r0, r1, r2, 0);
}

// ---------------------------------------------------------------------------
__global__ void __launch_bounds__(TPB, 5)
fused(const float* __restrict__ pts,
      const int* __restrict__ x0, const int* __restrict__ x1,
      const int* __restrict__ x2, const int* __restrict__ x3,
      const float* __restrict__ f0, const float* __restrict__ f1,
      const float* __restrict__ f2, const float* __restrict__ f3,
      float* __restrict__ out)
{
    int gtid = blockIdx.x * TPB + threadIdx.x;
    const float OFF = -0.48f;                        // (-0.5*0.015f)*64, exact

    // ---- phase 0: init ----
    if (gtid == 0) g_wl_cnt = 0;
    for (int i = gtid; i < MCELLS; i += NTHREADS)
        g_map[i] = make_int4(INF_I, INF_I, INF_I, INF_I);
    grid_bar(0);

    // ---- phase 1: scatter rows (3 lowest rows per cell, sorted) ----
    if (gtid < NROWS) {
        int t = gtid;
        const int* inds; int g, base, row;
        if (t < 16000)      { inds = x0; g = 32; base = MB0; row = t; }
        else if (t < 20000) { inds = x1; g = 16; base = MB1; row = t - 16000; }
        else if (t < 20512) { inds = x2; g = 8;  base = MB2; row = t - 20000; }
        else                { inds = x3; g = 4;  base = MB3; row = t - 20512; }
        int4 v = ((const int4*)inds)[row];           // [batch, ix, iy, iz]
        int* s = (int*)&g_map[base + (v.y * g + v.z) * g + v.w];
        int cur = row;
#pragma unroll
        for (int k = 0; k < 3; k++) {
            int old = atomicMin(&s[k], cur);
            cur = max(old, cur);
            if (cur == INF_I) break;
        }
    }
    grid_bar(1);

    // ---- phase 2: quad-per-task 27-cell search ----
    if (gtid < NTASKS * 4) {
        int task = gtid >> 2;                        // 4 lanes per task
        int ql   = gtid & 3;                         // quad lane 0..3
        int scale = task >> 13, point = task & (NPTS - 1);  // scale-major
        const float* f; float vs; int g, base;
        scale_params(scale, f0, f1, f2, f3, f, vs, g, base);
        const float HALF = 0.5f * vs;

        float px = __ldg(&pts[point * 3 + 0]);
        float py = __ldg(&pts[point * 3 + 1]);
        float pz = __ldg(&pts[point * 3 + 2]);

        int cx = min(g - 1, max(0, (int)floorf((px - OFF) / vs)));
        int cy = min(g - 1, max(0, (int)floorf((py - OFF) / vs)));
        int cz = min(g - 1, max(0, (int)floorf((pz - OFF) / vs)));

        float d0 = CUDART_INF_F, d1 = CUDART_INF_F, d2 = CUDART_INF_F;
        int   r0 = INF_I,        r1 = INF_I,        r2 = INF_I;

        // lanes take cells ql, ql+4, ..., < 27  (7,7,7,6 cells)
#pragma unroll
        for (int k = 0; k < 7; k++) {
            int i = ql + k * 4;
            if (i < 27) {
                int dz = i % 3 - 1;
                int r3 = i / 3;
                int dy = r3 % 3 - 1;
                int dx = r3 / 3 - 1;
                visit_cell(cx + dx, cy + dy, cz + dz, g, base, vs, OFF, HALF,
                           px, py, pz, d0, r0, d1, r1, d2, r2);
            }
        }

        // 2-step butterfly merge within the quad (disjoint keys each step);
        // all 4 lanes converge to the identical sorted top-3.
#pragma unroll
        for (int off = 1; off <= 2; off <<= 1) {
            float e0 = __shfl_xor_sync(0xffffffffu, d0, off);
            float e1 = __shfl_xor_sync(0xffffffffu, d1, off);
            float e2 = __shfl_xor_sync(0xffffffffu, d2, off);
            int   j0 = __shfl_xor_sync(0xffffffffu, r0, off);
            int   j1 = __shfl_xor_sync(0xffffffffu, r1, off);
            int   j2 = __shfl_xor_sync(0xffffffffu, r2, off);
            ins3(e0, j0, d0, r0, d1, r1, d2, r2);
            ins3(e1, j1, d0, r0, d1, r1, d2, r2);
            ins3(e2, j2, d0, r0, d1, r1, d2, r2);
        }

        if (ql == 0) {
            float b  = 1.5f * vs * 0.999999f;
            float b2 = b * b;
            if ((int)(d0 < b2) + (int)(d1 < b2) + (int)(d2 < b2) >= 3) {
                store_result(task, d0, d1, d2, r0, r1, r2);
            } else {
                g_wl[atomicAdd(&g_wl_cnt, 1u)] = task;   // rare fallback
            }
        }
    }
    grid_bar(2);

    // ---- phase 3: warp-cooperative ring search for worklist tasks ----
    {
        int warp = gtid >> 5;
        int lane = threadIdx.x & 31;
        unsigned wln = *(volatile unsigned*)&g_wl_cnt;

        for (unsigned e = warp; e < wln; e += NWARPS) {
            int task = g_wl[e];
            int scale = task >> 13, point = task & (NPTS - 1);
            const float* f; float vs; int g, base;
            scale_params(scale, f0, f1, f2, f3, f, vs, g, base);
            const float HALF = 0.5f * vs;

            float px = __ldg(&pts[point * 3 + 0]);
            float py = __ldg(&pts[point * 3 + 1]);
            float pz = __ldg(&pts[point * 3 + 2]);

            int cx = min(g - 1, max(0, (int)floorf((px - OFF) / vs)));
            int cy = min(g - 1, max(0, (int)floorf((py - OFF) / vs)));
            int cz = min(g - 1, max(0, (int)floorf((pz - OFF) / vs)));

            float d0 = CUDART_INF_F, d1 = CUDART_INF_F, d2 = CUDART_INF_F;
            int   r0 = INF_I,        r1 = INF_I,        r2 = INF_I;

            int rr = 1;
            bool first = true;
            while (true) {
                int side = 2 * rr + 1;
                int nc = side * side * side;
                for (int i = lane; i < nc; i += 32) {
                    int t = i;
                    int dz = t % side; t /= side;
                    int dy = t % side;
                    int dx = t / side;
                    dx -= rr; dy -= rr; dz -= rr;
                    if (!first) {
                        int ch = max(max(abs(dx), abs(dy)), abs(dz));
                        if (ch < rr) continue;
                    }
                    visit_cell(cx + dx, cy + dy, cz + dz, g, base, vs, OFF,
                               HALF, px, py, pz, d0, r0, d1, r1, d2, r2);
                }
                float bb  = ((float)rr + 0.5f) * vs * 0.999999f;
                float bb2 = bb * bb;
                int c = (int)(d0 < bb2) + (int)(d1 < bb2) + (int)(d2 < bb2);
                if (__reduce_add_sync(0xffffffffu, c) >= 3) break;
                if (rr >= g) break;                  // full grid -> exact
                rr++;
                first = false;
            }

            // REDUX 3-way head merge (rows unique across lanes)
            unsigned h0 = __float_as_uint(d0), h1 = __float_as_uint(d1),
                     h2 = __float_as_uint(d2);
            float wd[3]; int wr[3];
#pragma unroll
            for (int k = 0; k < 3; k++) {
                unsigned m  = __reduce_min_sync(0xffffffffu, h0);
                unsigned rm = __reduce_min_sync(0xffffffffu,
                                  (h0 == m) ? (unsigned)r0 : (unsigned)INF_I);
                wd[k] = __uint_as_float(m); wr[k] = (int)rm;
                if (h0 == m && (unsigned)r0 == rm) {
                    h0 = h1; r0 = r1; h1 = h2; r1 = r2; h2 = INF_FB; r2 = INF_I;
                }
            }
            if (lane == 0)
                store_result(task, wd[0], wd[1], wd[2], wr[0], wr[1], wr[2]);
        }
    }
    grid_bar(3);

    // ---- phase 4: thread-per-float4 gather (coalesced) ----
    for (int i = gtid; i < NF4; i += NTHREADS) {
        int point = i / 120;
        int c4 = i - point * 120;

        int scale, local, C4; const float* f;
        if (c4 < 8)       { scale = 0; local = c4;      C4 = 8;  f = f0; }
        else if (c4 < 24) { scale = 1; local = c4 - 8;  C4 = 16; f = f1; }
        else if (c4 < 56) { scale = 2; local = c4 - 24; C4 = 32; f = f2; }
        else              { scale = 3; local = c4 - 56; C4 = 64; f = f3; }

        int sidx = (scale << 13) | point;
        float4 w = g_w[sidx];
        int4   r = g_r[sidx];
        const float4* F = (const float4*)f;
        float4 a = F[r.x * C4 + local];
        float4 b = F[r.y * C4 + local];
        float4 d = F[r.z * C4 + local];
        float4 o;
        o.x = w.x * a.x + w.y * b.x + w.z * d.x;
        o.y = w.x * a.y + w.y * b.y + w.z * d.y;
        o.z = w.x * a.z + w.y * b.z + w.z * d.z;
        o.w = w.x * a.w + w.y * b.w + w.z * d.w;
        ((float4*)out)[i] = o;
    }
}

// ---------------------------------------------------------------------------
// Inputs identified by element count (all ten distinct):
//   points 24576 | batch_ids 8192 (all-zero, unused by reference)
//   indices: 64000 / 16000 / 2048 / 256
//   feats:   512000 / 256000 / 65536 / 16384
// ---------------------------------------------------------------------------
extern "C" void kernel_launch(void* const* d_in, const int* in_sizes, int n_in,
                              void* d_out, int out_size)
{
    const float* points = nullptr;
    const int* idx[4] = {nullptr, nullptr, nullptr, nullptr};
    const float* feats[4] = {nullptr, nullptr, nullptr, nullptr};

    for (int i = 0; i < n_in; i++) {
        switch (in_sizes[i]) {
            case 24576:  points   = (const float*)d_in[i]; break;
            case 64000:  idx[0]   = (const int*)d_in[i];   break;
            case 16000:  idx[1]   = (const int*)d_in[i];   break;
            case 2048:   idx[2]   = (const int*)d_in[i];   break;
            case 256:    idx[3]   = (const int*)d_in[i];   break;
            case 512000: feats[0] = (const float*)d_in[i]; break;
            case 256000: feats[1] = (const float*)d_in[i]; break;
            case 65536:  feats[2] = (const float*)d_in[i]; break;
            case 16384:  feats[3] = (const float*)d_in[i]; break;
            default: break; // batch_ids unused
        }
    }

    fused<<<GRID, TPB>>>(points, idx[0], idx[1], idx[2], idx[3],
                         feats[0], feats[1], feats[2], feats[3],
                         (float*)d_out);
}